// round 2
// baseline (speedup 1.0000x reference)
#include <cuda_runtime.h>
#include <cuda_bf16.h>

// Problem constants (from reference_code)
#define N_PATHS  10000000
#define MAX_LEN  3
#define N_NODES  100000
#define HIDDEN   128

// Scratch: projection table proj[node][l] = dot(node_feature[node], W[l][0]),
// 100000 * 3 floats = 1.2 MB. Static __device__ global (no allocation allowed).
__device__ float g_proj[N_NODES * MAX_LEN];

// ---------------------------------------------------------------------------
// Kernel 1: proj[node][l] = sum_d feature[node][d] * W[l][0][d]
// One warp per node. Lane t covers dims [4t, 4t+4) via float4.
// ---------------------------------------------------------------------------
__global__ void proj_kernel(const float* __restrict__ nf,
                            const float* __restrict__ W) {
    const int lane   = threadIdx.x & 31;
    const int warpIn = threadIdx.x >> 5;
    const int node   = blockIdx.x * (blockDim.x >> 5) + warpIn;
    if (node >= N_NODES) return;

    const float4 w0 = __ldg(((const float4*)W) + 0  + lane);  // l = 0
    const float4 w1 = __ldg(((const float4*)W) + 32 + lane);  // l = 1
    const float4 w2 = __ldg(((const float4*)W) + 64 + lane);  // l = 2

    const float4 f = __ldg(((const float4*)nf) + (size_t)node * 32 + lane);

    float s0 = f.x * w0.x + f.y * w0.y + f.z * w0.z + f.w * w0.w;
    float s1 = f.x * w1.x + f.y * w1.y + f.z * w1.z + f.w * w1.w;
    float s2 = f.x * w2.x + f.y * w2.y + f.z * w2.z + f.w * w2.w;

    #pragma unroll
    for (int o = 16; o > 0; o >>= 1) {
        s0 += __shfl_xor_sync(0xFFFFFFFFu, s0, o);
        s1 += __shfl_xor_sync(0xFFFFFFFFu, s1, o);
        s2 += __shfl_xor_sync(0xFFFFFFFFu, s2, o);
    }

    if (lane == 0) {
        g_proj[node * 3 + 0] = s0;
        g_proj[node * 3 + 1] = s1;
        g_proj[node * 3 + 2] = s2;
    }
}

// ---------------------------------------------------------------------------
// Kernel 2: per-path gather + masked mean.
// paths is int32 (JAX downcasts int64 without x64 enabled).
// Each thread handles 4 paths: 12 int32 = 48 B = 3x int4 (coalesced),
// then up to 12 random scalar gathers into the 1.2 MB g_proj table,
// output written as one float4.
// ---------------------------------------------------------------------------
__global__ void gather_kernel(const int* __restrict__ paths,
                              float* __restrict__ out) {
    const long long tid = (long long)blockIdx.x * blockDim.x + threadIdx.x;
    if (tid >= (N_PATHS / 4)) return;

    const int4* p4 = ((const int4*)paths) + tid * 3;
    int4 v0 = __ldg(p4 + 0);
    int4 v1 = __ldg(p4 + 1);
    int4 v2 = __ldg(p4 + 2);

    int idx[12] = { v0.x, v0.y, v0.z, v0.w,
                    v1.x, v1.y, v1.z, v1.w,
                    v2.x, v2.y, v2.z, v2.w };

    float4 res;
    float* r = (float*)&res;

    #pragma unroll
    for (int k = 0; k < 4; k++) {
        float s = 0.0f;
        int   cnt = 0;
        #pragma unroll
        for (int l = 0; l < 3; l++) {
            int p = idx[k * 3 + l];
            if (p >= 0 && p < N_NODES) {   // bounds guard: safe even if dtype assumption is wrong
                s += __ldg(&g_proj[p * 3 + l]);
                cnt++;
            }
        }
        int len = (cnt > 0) ? cnt : 1;
        r[k] = s / (float)len;
    }

    ((float4*)out)[tid] = res;
}

// ---------------------------------------------------------------------------
// Launch. Inputs identified by element count (robust to metadata ordering):
//   30,000,000 -> paths  [10M, 3]
//   12,800,000 -> node_feature [100000, 128] f32
//          384 -> W [3, 1, 128] f32
// ---------------------------------------------------------------------------
extern "C" void kernel_launch(void* const* d_in, const int* in_sizes, int n_in,
                              void* d_out, int out_size) {
    const void*  paths_raw = nullptr;
    const float* nf        = nullptr;
    const float* W         = nullptr;

    for (int i = 0; i < n_in; i++) {
        if      (in_sizes[i] == N_PATHS * MAX_LEN)  paths_raw = d_in[i];
        else if (in_sizes[i] == N_NODES * HIDDEN)   nf        = (const float*)d_in[i];
        else if (in_sizes[i] == MAX_LEN * HIDDEN)   W         = (const float*)d_in[i];
    }

    float* out = (float*)d_out;  // f32 [10M]

    // proj: 100000 nodes, 8 warps (256 threads) per block -> one warp per node
    {
        const int threads = 256;
        const int warpsPerBlock = threads / 32;
        const int blocks = (N_NODES + warpsPerBlock - 1) / warpsPerBlock;
        proj_kernel<<<blocks, threads>>>(nf, W);
    }

    // gather: 2.5M threads, 4 paths each
    {
        const int threads = 256;
        const long long nThreads = N_PATHS / 4;
        const int blocks = (int)((nThreads + threads - 1) / threads);
        gather_kernel<<<blocks, threads>>>((const int*)paths_raw, out);
    }
}